// round 16
// baseline (speedup 1.0000x reference)
#include <cuda_runtime.h>
#include <cuda_fp16.h>
#include <mma.h>
#include <math.h>

using namespace nvcuda;

// ---------------- problem constants ----------------
namespace {
constexpr int N   = 10000;
constexpr int E   = 160000;
constexpr int C   = 64;
constexpr int LM  = 9;
constexpr int CAP = 64;          // bucket capacity (max degree ~40 for Poisson(16))
constexpr float RMAX    = 5.0f;
constexpr float INV_AVG = 1.0f / 16.0f;
constexpr float S3      = 1.7320508f;
constexpr float PI_F    = 3.14159265358979f;
constexpr float PREF    = 0.63245553203f; // sqrt(2/RMAX)
}

// ---------------- device scratch (static, no allocation) ----------------
__device__ float  g_h1[N * C];
__device__ float  g_sc[N * C];
__device__ float  g_q [N * C];
__device__ float4 g_ub[(size_t)N * CAP];        // bucket-ordered unit vectors
__device__ __half g_Rb[(size_t)N * CAP * C];    // bucket-ordered R (fp16)
__device__ int    g_send[(size_t)N * CAP];      // bucket-ordered senders
__device__ int    g_cnt[N];

// ---------------- kernels ----------------

// zero counters + output bins
__global__ void k_prep(float* __restrict__ out, int out_size) {
    int i = blockIdx.x * blockDim.x + threadIdx.x;
    if (i < N) g_cnt[i] = 0;
    if (i < out_size) out[i] = 0.0f;
}

// Fused edge kernel: geometry, bucket slot assign, radial basis, radial MLP.
// GEMM1 scalar fp32; GEMM2 on tensor cores. R/u/sender stored BUCKET-ORDERED.
__global__ __launch_bounds__(256) void k_edge_radial(
    const float* __restrict__ pos, const int* __restrict__ ei,
    const float* __restrict__ W1, const float* __restrict__ b1,
    const float* __restrict__ W2)
{
    __shared__ float sW1[8 * 64];
    __shared__ float sB[64];
    __shared__ __align__(16) __half sW2h[64 * 72];    // [k][c], stride 72
    __shared__ __align__(16) __half sHidE[128 * 72];  // [edge][k], stride 72
    __shared__ int sPos[128];                         // bucket position per edge
    __shared__ __align__(16) union {
        float ef[8 * 128];            // [k][edge] radial basis (GEMM1 input)
        float outbuf[8][16][36];      // per-warp wmma staging (after GEMM1)
    } U;

    int tid = threadIdx.x;
    int lane = tid & 31;
    int w = tid >> 5;                 // warp id 0..7
    int e0 = blockIdx.x * 128;
    int el = tid & 127;
    int e = e0 + el;

    for (int i = tid; i < 512; i += 256) sW1[i] = W1[i];
    if (tid < 64) sB[tid] = b1[tid];
    for (int i = tid; i < 4096; i += 256)
        sW2h[(i >> 6) * 72 + (i & 63)] = __float2half(W2[i]);

    // geometry (computed redundantly by the 2 thread-slices; cheap)
    int s = ei[e];
    int r = ei[E + e];
    float dx = pos[r * 3 + 0] - pos[s * 3 + 0];
    float dy = pos[r * 3 + 1] - pos[s * 3 + 1];
    float dz = pos[r * 3 + 2] - pos[s * 3 + 2];
    float rr = sqrtf(dx * dx + dy * dy + dz * dz);
    float rinv = 1.0f / fmaxf(rr, 1e-9f);
    float x = dx * rinv, y = dy * rinv, z = dz * rinv;

    if (tid < 128) {
        int slot = atomicAdd(&g_cnt[r], 1);
        int p = (slot < CAP) ? (r * CAP + slot) : -1;
        sPos[el] = p;
        if (p >= 0) {
            g_ub[p] = make_float4(x, y, z, 0.0f);
            g_send[p] = s;
        }
    }

    // radial basis: 2 thread-slices x 4 sines each -> U.ef [k][edge]
    {
        float xx = rr * (1.0f / RMAX);
        float env = 0.0f;
        if (xx < 1.0f) {
            float x2 = xx * xx, x3 = x2 * xx;
            float x6 = x3 * x3, x7 = x6 * xx, x8 = x7 * xx;
            env = 1.0f - 28.0f * x6 + 48.0f * x7 - 21.0f * x8;
        }
        float wq = rr * (PI_F / RMAX);
        float pe = PREF * rinv * env;
        int j = tid >> 7;   // 0 or 1
#pragma unroll
        for (int m = 0; m < 4; m++)
            U.ef[(4 * j + m) * 128 + el] = pe * sinf((float)(4 * j + m + 1) * wq);
    }
    __syncthreads();

    int eg = tid & 15;   // edge group: 8 edges
    int g2 = tid >> 4;   // hidden quad

    // GEMM1: hid[el][h] = silu(b[h] + sum_k ef[el][k]*W1[k][h]) -> fp16 [edge][k]
    {
        float acc[4][8];
#pragma unroll
        for (int hi = 0; hi < 4; hi++) {
            float b = sB[g2 * 4 + hi];
#pragma unroll
            for (int ej = 0; ej < 8; ej++) acc[hi][ej] = b;
        }
#pragma unroll
        for (int k = 0; k < 8; k++) {
            float4 ea = *(const float4*)&U.ef[k * 128 + eg * 8];
            float4 eb = *(const float4*)&U.ef[k * 128 + eg * 8 + 4];
            float4 w4 = *(const float4*)&sW1[k * 64 + g2 * 4];
            float ee[8] = {ea.x, ea.y, ea.z, ea.w, eb.x, eb.y, eb.z, eb.w};
            float ww[4] = {w4.x, w4.y, w4.z, w4.w};
#pragma unroll
            for (int hi = 0; hi < 4; hi++)
#pragma unroll
                for (int ej = 0; ej < 8; ej++)
                    acc[hi][ej] = fmaf(ww[hi], ee[ej], acc[hi][ej]);
        }
#pragma unroll
        for (int hi = 0; hi < 4; hi++)
#pragma unroll
            for (int ej = 0; ej < 8; ej++) {
                float a = acc[hi][ej];
                float v = a / (1.0f + expf(-a));
                sHidE[(eg * 8 + ej) * 72 + g2 * 4 + hi] = __float2half(v);
            }
    }
    __syncthreads();

    // GEMM2 on tensor cores: R[edge][c] = hid @ W2, stored at bucket position.
    {
        wmma::fragment<wmma::matrix_a, 16, 16, 16, __half, wmma::row_major> fa[4];
#pragma unroll
        for (int kf = 0; kf < 4; kf++)
            wmma::load_matrix_sync(fa[kf], &sHidE[(w * 16) * 72 + kf * 16], 72);

#pragma unroll
        for (int nh = 0; nh < 2; nh++) {
            wmma::fragment<wmma::accumulator, 16, 16, 16, float> fc0, fc1;
            wmma::fill_fragment(fc0, 0.0f);
            wmma::fill_fragment(fc1, 0.0f);
#pragma unroll
            for (int kf = 0; kf < 4; kf++) {
                wmma::fragment<wmma::matrix_b, 16, 16, 16, __half, wmma::row_major> fb0, fb1;
                wmma::load_matrix_sync(fb0, &sW2h[kf * 16 * 72 + nh * 32], 72);
                wmma::load_matrix_sync(fb1, &sW2h[kf * 16 * 72 + nh * 32 + 16], 72);
                wmma::mma_sync(fc0, fa[kf], fb0, fc0);
                wmma::mma_sync(fc1, fa[kf], fb1, fc1);
            }
            wmma::store_matrix_sync(&U.outbuf[w][0][0],  fc0, 36, wmma::mem_row_major);
            wmma::store_matrix_sync(&U.outbuf[w][0][16], fc1, 36, wmma::mem_row_major);
            __syncwarp();

            int rrow = lane >> 1;
            int hh = lane & 1;
            const float* rowp = &U.outbuf[w][rrow][hh * 16];
            int p = sPos[w * 16 + rrow];
            if (p >= 0) {
                __half2* dst = (__half2*)&g_Rb[(size_t)p * C + nh * 32 + hh * 16];
#pragma unroll
                for (int j = 0; j < 8; j++)
                    dst[j] = __floats2half2_rn(rowp[2 * j], rowp[2 * j + 1]);
            }
            __syncwarp();
        }
    }
}

// layer-0 linear with fused embedding: h = W_embed[type], h1 = h@W_up, sc = h@W_sc.
__global__ __launch_bounds__(128) void k_linear0(
    const float* __restrict__ Wup, const float* __restrict__ Wsc,
    const float* __restrict__ W_embed, const int* __restrict__ types) {
    __shared__ __align__(16) __half sWu[64 * 72];
    __shared__ __align__(16) __half sWs[64 * 72];
    __shared__ __align__(16) __half sH [64 * 72];

    int tid = threadIdx.x;
    int w = tid >> 5;
    int n0 = blockIdx.x * 64;

    for (int i = tid; i < 4096; i += 128) {
        int k = i >> 6, c = i & 63;
        sWu[k * 72 + c] = __float2half(Wup[i]);
        sWs[k * 72 + c] = __float2half(Wsc[i]);
        int n = n0 + k;
        float hv = 0.0f;
        if (n < N) hv = W_embed[types[n] * 64 + c];
        sH[k * 72 + c] = __float2half(hv);
    }
    __syncthreads();

    int nb = n0 + w * 16;
    if (nb < N) {
        wmma::fragment<wmma::matrix_a, 16, 16, 16, __half, wmma::row_major> fa[4];
#pragma unroll
        for (int kf = 0; kf < 4; kf++)
            wmma::load_matrix_sync(fa[kf], &sH[(w * 16) * 72 + kf * 16], 72);

#pragma unroll
        for (int nt = 0; nt < 4; nt++) {
            wmma::fragment<wmma::accumulator, 16, 16, 16, float> cu, cs;
            wmma::fill_fragment(cu, 0.0f);
            wmma::fill_fragment(cs, 0.0f);
#pragma unroll
            for (int kf = 0; kf < 4; kf++) {
                wmma::fragment<wmma::matrix_b, 16, 16, 16, __half, wmma::row_major> fu, fs;
                wmma::load_matrix_sync(fu, &sWu[kf * 16 * 72 + nt * 16], 72);
                wmma::load_matrix_sync(fs, &sWs[kf * 16 * 72 + nt * 16], 72);
                wmma::mma_sync(cu, fa[kf], fu, cu);
                wmma::mma_sync(cs, fa[kf], fs, cs);
            }
            wmma::store_matrix_sync(&g_h1[nb * 64 + nt * 16], cu, 64, wmma::mem_row_major);
            wmma::store_matrix_sync(&g_sc[nb * 64 + nt * 16], cs, 64, wmma::mem_row_major);
        }
    }
}

// TENSOR-CORE gather: per node, A(16xC) = sh^T (16 x k) @ t (k x C) with
// k = edge chunks of 16. t = R*h1[send] built fp16 in smem (R/u/send reads are
// bucket-ordered = streaming). 1 warp per node, 4 nodes/block.
__global__ __launch_bounds__(128) void k_gather() {
    __shared__ __align__(32) __half sSh[4][16 * 24];   // [lm][edge] fp16 per warp
    __shared__ __align__(32) __half sT [4][16 * 72];   // [edge][ch] fp16 per warp
    __shared__ __align__(32) float  sA [4][16 * 68];   // [lm][ch] fp32 result

    int w    = threadIdx.x >> 5;
    int lane = threadIdx.x & 31;
    int n    = blockIdx.x * 4 + w;
    int cnt  = g_cnt[n];
    if (cnt > CAP) cnt = CAP;
    size_t base = (size_t)n * CAP;

    wmma::fragment<wmma::accumulator, 16, 16, 16, float> acc[4];
#pragma unroll
    for (int t = 0; t < 4; t++) wmma::fill_fragment(acc[t], 0.0f);

    for (int k0 = 0; k0 < cnt; k0 += 16) {
        // sh chunk: lane < 16 owns edge column e = lane
        if (lane < 16) {
            int i = k0 + lane;
            bool v = i < cnt;
            float x = 0.f, y = 0.f, z = 0.f, one = 0.f;
            if (v) {
                float4 u4 = __ldg(&g_ub[base + i]);   // sequential
                x = u4.x; y = u4.y; z = u4.z; one = 1.0f;
            }
            float shv[LM] = {one, x, y, z,
                             S3 * x * y, S3 * y * z,
                             0.5f * (3.0f * z * z - one), S3 * x * z,
                             0.5f * S3 * (x * x - y * y)};
#pragma unroll
            for (int lm = 0; lm < LM; lm++)
                sSh[w][lm * 24 + lane] = __float2half(shv[lm]);
#pragma unroll
            for (int lm = LM; lm < 16; lm++)
                sSh[w][lm * 24 + lane] = __float2half(0.0f);
        }
        // t chunk: all 32 lanes, 2 channels each
#pragma unroll
        for (int e = 0; e < 16; e++) {
            int i = k0 + e;
            __half2 tv = __floats2half2_rn(0.0f, 0.0f);
            if (i < cnt) {
                int s = __ldg(&g_send[base + i]);                     // uniform
                float2 rv = __half22float2(
                    *(const __half2*)&g_Rb[(base + i) * C + 2 * lane]); // stream
                float2 hv = *(const float2*)&g_h1[s * C + 2 * lane];    // L2
                tv = __floats2half2_rn(rv.x * hv.x, rv.y * hv.y);
            }
            *(__half2*)&sT[w][e * 72 + 2 * lane] = tv;
        }
        __syncwarp();

        wmma::fragment<wmma::matrix_a, 16, 16, 16, __half, wmma::row_major> fa;
        wmma::load_matrix_sync(fa, &sSh[w][0], 24);
#pragma unroll
        for (int t = 0; t < 4; t++) {
            wmma::fragment<wmma::matrix_b, 16, 16, 16, __half, wmma::row_major> fb;
            wmma::load_matrix_sync(fb, &sT[w][t * 16], 72);
            wmma::mma_sync(acc[t], fa, fb, acc[t]);
        }
        __syncwarp();
    }

#pragma unroll
    for (int t = 0; t < 4; t++)
        wmma::store_matrix_sync(&sA[w][t * 16], acc[t], 68, wmma::mem_row_major);
    __syncwarp();

    // epilogue: q[c] = A0 + sum_lm A^2, 2 channels per lane
    float a0 = sA[w][2 * lane]     * INV_AVG;
    float a1 = sA[w][2 * lane + 1] * INV_AVG;
    float q0 = fmaf(a0, a0, a0);
    float q1 = fmaf(a1, a1, a1);
#pragma unroll
    for (int lm = 1; lm < LM; lm++) {
        a0 = sA[w][lm * 68 + 2 * lane]     * INV_AVG;
        a1 = sA[w][lm * 68 + 2 * lane + 1] * INV_AVG;
        q0 = fmaf(a0, a0, q0);
        q1 = fmaf(a1, a1, q1);
    }
    *(float2*)&g_q[n * C + 2 * lane] = make_float2(q0, q1);
}

// Fused update(+linear of next layer): h = q@W_prod + sc (tensor cores, h kept
// in SMEM only); energy dot -> per-graph bins; if DO_LIN, h1/sc for next layer
// computed in-block. 64 nodes/block, 8 warps.
template<bool DO_LIN>
__global__ __launch_bounds__(256) void k_upd(
    const float* __restrict__ Wp, const float* __restrict__ wro,
    const int* __restrict__ batch, float* __restrict__ out,
    const float* __restrict__ Wup, const float* __restrict__ Wsc)
{
    __shared__ __align__(16) __half sWp[64 * 72];
    __shared__ __align__(16) __half sQH[64 * 72];      // q (phase U), then h (phase L)
    __shared__ __align__(16) union {
        float D[64 * 68];                               // update GEMM result
        __half Wx[2 * 64 * 72];                         // then Wup|Wsc fp16
    } A;
    __shared__ __align__(16) float sWro[64];

    int tid = threadIdx.x;
    int w = tid >> 5;
    int n0 = blockIdx.x * 64;

    for (int i = tid; i < 4096; i += 256) {
        int k = i >> 6, c = i & 63;
        sWp[k * 72 + c] = __float2half(Wp[i]);
        int n = n0 + k;
        sQH[k * 72 + c] = __float2half((n < N) ? g_q[n * 64 + c] : 0.0f);
    }
    if (tid < 64) sWro[tid] = wro[tid];
    __syncthreads();

    // Phase U: D = q @ Wp. 16 tiles (4 rows x 4 cols) over 8 warps, 2 each.
#pragma unroll
    for (int t = 0; t < 2; t++) {
        int tile = w * 2 + t;
        int tr = tile >> 2, tc = tile & 3;
        if (n0 + tr * 16 < N) {
            wmma::fragment<wmma::accumulator, 16, 16, 16, float> fc;
            wmma::fill_fragment(fc, 0.0f);
#pragma unroll
            for (int kf = 0; kf < 4; kf++) {
                wmma::fragment<wmma::matrix_a, 16, 16, 16, __half, wmma::row_major> fa;
                wmma::fragment<wmma::matrix_b, 16, 16, 16, __half, wmma::row_major> fb;
                wmma::load_matrix_sync(fa, &sQH[(tr * 16) * 72 + kf * 16], 72);
                wmma::load_matrix_sync(fb, &sWp[(kf * 16) * 72 + tc * 16], 72);
                wmma::mma_sync(fc, fa, fb, fc);
            }
            wmma::store_matrix_sync(&A.D[(tr * 16) * 68 + tc * 16], fc, 68,
                                    wmma::mem_row_major);
        }
    }
    __syncthreads();

    // Epilogue: 4 threads/node, 16 ch each: h = D + sc; energy; h -> sQH fp16
    {
        int nl = tid >> 2, qh = tid & 3;
        int n = n0 + nl;
        float part = 0.0f;
        if (n < N) {
#pragma unroll
            for (int j = 0; j < 4; j++) {
                int c = qh * 16 + j * 4;
                float4 d4 = *(const float4*)&A.D[nl * 68 + c];
                float4 s4 = *(const float4*)&g_sc[n * 64 + c];
                float h0 = d4.x + s4.x, h1v = d4.y + s4.y;
                float h2 = d4.z + s4.z, h3 = d4.w + s4.w;
                float4 w4 = *(const float4*)&sWro[c];
                part += h0 * w4.x + h1v * w4.y + h2 * w4.z + h3 * w4.w;
                if (DO_LIN) {
                    *(__half2*)&sQH[nl * 72 + c]     = __floats2half2_rn(h0, h1v);
                    *(__half2*)&sQH[nl * 72 + c + 2] = __floats2half2_rn(h2, h3);
                }
            }
        }
        part += __shfl_xor_sync(0xffffffffu, part, 1);
        part += __shfl_xor_sync(0xffffffffu, part, 2);
        if ((tid & 3) == 0 && n < N) atomicAdd(&out[batch[n]], part);
    }

    if (DO_LIN) {
        __syncthreads();   // D fully consumed; sQH now holds h
        for (int i = tid; i < 4096; i += 256) {
            int k = i >> 6, c = i & 63;
            A.Wx[k * 72 + c]           = __float2half(Wup[i]);
            A.Wx[64 * 72 + k * 72 + c] = __float2half(Wsc[i]);
        }
        __syncthreads();

        // Phase L: h1 = h@Wup, sc = h@Wsc. warp w: row = w>>1, 2 col tiles.
        int tr = w >> 1;
        if (n0 + tr * 16 < N) {
            wmma::fragment<wmma::matrix_a, 16, 16, 16, __half, wmma::row_major> fa[4];
#pragma unroll
            for (int kf = 0; kf < 4; kf++)
                wmma::load_matrix_sync(fa[kf], &sQH[(tr * 16) * 72 + kf * 16], 72);
#pragma unroll
            for (int cc = 0; cc < 2; cc++) {
                int tc = (w & 1) * 2 + cc;
                wmma::fragment<wmma::accumulator, 16, 16, 16, float> cu, cs;
                wmma::fill_fragment(cu, 0.0f);
                wmma::fill_fragment(cs, 0.0f);
#pragma unroll
                for (int kf = 0; kf < 4; kf++) {
                    wmma::fragment<wmma::matrix_b, 16, 16, 16, __half, wmma::row_major> fu, fs;
                    wmma::load_matrix_sync(fu, &A.Wx[(kf * 16) * 72 + tc * 16], 72);
                    wmma::load_matrix_sync(fs, &A.Wx[64 * 72 + (kf * 16) * 72 + tc * 16], 72);
                    wmma::mma_sync(cu, fa[kf], fu, cu);
                    wmma::mma_sync(cs, fa[kf], fs, cs);
                }
                int nb = n0 + tr * 16;
                wmma::store_matrix_sync(&g_h1[nb * 64 + tc * 16], cu, 64, wmma::mem_row_major);
                wmma::store_matrix_sync(&g_sc[nb * 64 + tc * 16], cs, 64, wmma::mem_row_major);
            }
        }
    }
}

// ---------------- launcher ----------------
extern "C" void kernel_launch(void* const* d_in, const int* in_sizes, int n_in,
                              void* d_out, int out_size) {
    const float* pos     = (const float*)d_in[0];
    const float* W_embed = (const float*)d_in[1];
    const float* W_r1    = (const float*)d_in[2];
    const float* b_r1    = (const float*)d_in[3];
    const float* W_r2    = (const float*)d_in[4];
    const float* W_up    = (const float*)d_in[5];
    const float* W_sc    = (const float*)d_in[6];
    const float* W_prod  = (const float*)d_in[7];
    const float* w_ro    = (const float*)d_in[8];
    const int*   types   = (const int*)d_in[9];
    const int*   ei      = (const int*)d_in[10];
    const int*   batch   = (const int*)d_in[11];
    float* out = (float*)d_out;

    k_prep<<<(N + 255) / 256, 256>>>(out, out_size);
    k_edge_radial<<<E / 128, 256>>>(pos, ei, W_r1, b_r1, W_r2);
    k_linear0<<<(N + 63) / 64, 128>>>(W_up, W_sc, W_embed, types);

    k_gather<<<N / 4, 128>>>();
    k_upd<true><<<(N + 63) / 64, 256>>>(W_prod, w_ro, batch, out,
                                        W_up + C * C, W_sc + C * C);
    k_gather<<<N / 4, 128>>>();
    k_upd<false><<<(N + 63) / 64, 256>>>(W_prod + C * C, w_ro + C, batch, out,
                                         nullptr, nullptr);
}